// round 11
// baseline (speedup 1.0000x reference)
#include <cuda_runtime.h>
#include <cstdint>

// Problem constants
#define BATCH 32
#define NEXP 8
#define CIN 64
#define COUT 64
#define HW 25600            // 160*160
#define NTW 8               // pixels per warp-tile
#define ITERS 16            // tiles per warp -> 128-px strip
#define XSW 8               // smem row stride in floats (no pad needed)
#define TILEF (CIN * XSW)   // 512 floats = 2KB per stage
#define NBUF 4
#define WARPF (NBUF * TILEF)          // 8KB per warp
#define SMEM_BYTES (8 * WARPF * 4)    // 65536 -> 3 CTAs/SM

// Fragment-packed, TF32-rounded W: g_W2[b][(k*4+m)*32 + lane] =
//   {W[m16+g][k8+t], W[m16+8+g][k8+t], W[m16+g][k8+t+4], W[m16+8+g][k8+t+4]}
__device__ float4 g_W2[BATCH * 1024];

__device__ __forceinline__ uint32_t f2tf32(float f) {
    uint32_t r;
    asm("cvt.rna.tf32.f32 %0, %1;" : "=r"(r) : "f"(f));
    return r;
}
__device__ __forceinline__ float tf32r(float f) { return __uint_as_float(f2tf32(f)); }

__device__ __forceinline__ void cp_async16(float* dst_smem, const float* src_gmem) {
    uint32_t d = (uint32_t)__cvta_generic_to_shared(dst_smem);
    asm volatile("cp.async.cg.shared.global [%0], [%1], 16;\n" :: "r"(d), "l"(src_gmem));
}
__device__ __forceinline__ void cp_commit() {
    asm volatile("cp.async.commit_group;\n" ::: "memory");
}
template<int N> __device__ __forceinline__ void cp_wait() {
    asm volatile("cp.async.wait_group %0;\n" :: "n"(N) : "memory");
}

// Kernel 1: fragment-packed W with (1+3.38e-4) bias pre-scale + tf32-RNA.
// Scale cancels first-order truncation bias of raw-fp32 X bits in the tf32 MMA.
__global__ void lla_weights_kernel(const float* __restrict__ alpha,
                                   const float* __restrict__ ke) {
    const int b = blockIdx.x;
    __shared__ float a_s[NEXP];
    if (threadIdx.x < NEXP) a_s[threadIdx.x] = alpha[b * NEXP + threadIdx.x];
    __syncthreads();
#pragma unroll
    for (int ent = 0; ent < 4; ent++) {
        int id = ent * 256 + threadIdx.x;   // 0..1023
        int l  = id & 31;
        int km = id >> 5;                   // k*4 + m
        int m  = km & 3, k = km >> 2;
        int g  = l >> 2, t = l & 3;
        int r0 = m * 16 + g, r1 = r0 + 8;
        int c0 = k * 8 + t,  c1 = c0 + 4;
        float s00 = 0.f, s10 = 0.f, s01 = 0.f, s11 = 0.f;
#pragma unroll
        for (int e = 0; e < NEXP; e++) {
            const float* kb = ke + e * COUT * CIN;
            float a = a_s[e];
            s00 = fmaf(a, kb[r0 * 64 + c0], s00);
            s10 = fmaf(a, kb[r1 * 64 + c0], s10);
            s01 = fmaf(a, kb[r0 * 64 + c1], s01);
            s11 = fmaf(a, kb[r1 * 64 + c1], s11);
        }
        g_W2[b * 1024 + id] = make_float4(
            tf32r(s00 * 1.000338f), tf32r(s10 * 1.000338f),
            tf32r(s01 * 1.000338f), tf32r(s11 * 1.000338f));
    }
}

// Kernel 2: warp-autonomous tf32-mma pipelines, 3 CTAs/SM (24 warps), each
// warp a private depth-4 cp.async ring over 8-px tiles. M=64 x N=8 per tile.
// A-fragments from L1-hot g_W2; B smem layout naturally conflict-free.
__global__ __launch_bounds__(256, 3)
void lla_conv_kernel(const float* __restrict__ x, float* __restrict__ out) {
    extern __shared__ float smem[];

    const int b    = blockIdx.y;
    const int tid  = threadIdx.x;
    const int lane = tid & 31;
    const int warp = tid >> 5;
    const int g    = lane >> 2;     // 0..7
    const int tig  = lane & 3;      // 0..3

    const float*  xb   = x   + (size_t)b * CIN  * HW;
    float*        ob   = out + (size_t)b * COUT * HW;
    const float4* wf   = g_W2 + b * 1024 + lane;
    float* const  ring = smem + warp * WARPF;
    const int pw = (blockIdx.x * 8 + warp) * (NTW * ITERS);

    // ---- Prologue: tiles 0..2 into stages 0..2 ----
#pragma unroll
    for (int t = 0; t < NBUF - 1; t++) {
#pragma unroll
        for (int i = 0; i < 4; i++) {
            int id  = lane + 32 * i;        // 0..127
            int row = id >> 1;              // 0..63
            int q   = id & 1;               // 16B half of 32B row
            cp_async16(ring + t * TILEF + row * XSW + q * 4,
                       xb + row * HW + pw + t * NTW + q * 4);
        }
        cp_commit();
    }

    for (int it = 0; it < ITERS; it++) {
        float* const cur = ring + (it & (NBUF - 1)) * TILEF;
        const int p0 = pw + it * NTW;

        // ---- Prefetch tile it+3 into stage (it+3)&3, then always commit ----
        if (it + NBUF - 1 < ITERS) {
            float* const nxt = ring + ((it + NBUF - 1) & (NBUF - 1)) * TILEF;
            const int pn = p0 + (NBUF - 1) * NTW;
#pragma unroll
            for (int i = 0; i < 4; i++) {
                int id  = lane + 32 * i;
                int row = id >> 1;
                int q   = id & 1;
                cp_async16(nxt + row * XSW + q * 4, xb + row * HW + pn + q * 4);
            }
        }
        cp_commit();

        cp_wait<NBUF - 1>();   // tile 'it' resident (3 groups may remain)
        __syncwarp();

        // ---- Compute: 4 m-subtiles x 8 k-steps; W via L1 LDG.128 ----
        float acc[4][4];
#pragma unroll
        for (int m = 0; m < 4; m++) {
            acc[m][0] = 0.f; acc[m][1] = 0.f; acc[m][2] = 0.f; acc[m][3] = 0.f;
        }
#pragma unroll
        for (int k = 0; k < 8; k++) {
            uint32_t b0 = __float_as_uint(cur[(k * 8 + tig)     * XSW + g]);
            uint32_t b1 = __float_as_uint(cur[(k * 8 + 4 + tig) * XSW + g]);
#pragma unroll
            for (int m = 0; m < 4; m++) {
                float4 a = __ldg(wf + (k * 4 + m) * 32);
                asm volatile(
                    "mma.sync.aligned.m16n8k8.row.col.f32.tf32.tf32.f32 "
                    "{%0,%1,%2,%3}, {%4,%5,%6,%7}, {%8,%9}, {%0,%1,%2,%3};\n"
                    : "+f"(acc[m][0]), "+f"(acc[m][1]),
                      "+f"(acc[m][2]), "+f"(acc[m][3])
                    : "r"(__float_as_uint(a.x)), "r"(__float_as_uint(a.y)),
                      "r"(__float_as_uint(a.z)), "r"(__float_as_uint(a.w)),
                      "r"(b0), "r"(b1));
            }
        }

        // ---- Streaming stores: full 32B sectors across the warp ----
#pragma unroll
        for (int m = 0; m < 4; m++) {
            const int c = p0 + 2 * tig;
            float2 v0 = make_float2(acc[m][0], acc[m][1]);
            float2 v1 = make_float2(acc[m][2], acc[m][3]);
            __stcs(reinterpret_cast<float2*>(ob + (size_t)(m * 16 + g)     * HW + c), v0);
            __stcs(reinterpret_cast<float2*>(ob + (size_t)(m * 16 + 8 + g) * HW + c), v1);
        }
    }
}

extern "C" void kernel_launch(void* const* d_in, const int* in_sizes, int n_in,
                              void* d_out, int out_size) {
    const float* x     = (const float*)d_in[0];   // [32,64,160,160]
    const float* alpha = (const float*)d_in[1];   // [32,8]
    const float* ke    = (const float*)d_in[2];   // [8,64,64,1,1]
    float*       out   = (float*)d_out;           // [32,64,160,160]

    cudaFuncSetAttribute(lla_conv_kernel,
                         cudaFuncAttributeMaxDynamicSharedMemorySize, SMEM_BYTES);

    lla_weights_kernel<<<BATCH, 256>>>(alpha, ke);

    dim3 grid(HW / (8 * NTW * ITERS), BATCH);     // (25, 32)
    lla_conv_kernel<<<grid, 256, SMEM_BYTES>>>(x, out);
}

// round 16
// speedup vs baseline: 1.6141x; 1.6141x over previous
#include <cuda_runtime.h>
#include <cstdint>

// Problem constants
#define BATCH 32
#define NEXP 8
#define CIN 64
#define COUT 64
#define HW 25600            // 160*160
#define NPX 32              // pixels per CTA-tile
#define NT 32               // tiles per CTA -> 1024-px strip
#define XS 32               // smem row stride in floats (XOR-swizzled, no pad)
#define TILEF (CIN * XS)    // 2048 floats = 8KB per stage
#define NBUF 4
#define SMEM_BYTES (NBUF * TILEF * 4)   // 32768 -> 5 CTAs/SM

// Fragment-packed, TF32-rounded W: g_W2[b][(k*4+m)*32 + lane] =
//   {W[m16+g][k8+t], W[m16+8+g][k8+t], W[m16+g][k8+t+4], W[m16+8+g][k8+t+4]}
__device__ float4 g_W2[BATCH * 1024];

__device__ __forceinline__ uint32_t f2tf32(float f) {
    uint32_t r;
    asm("cvt.rna.tf32.f32 %0, %1;" : "=r"(r) : "f"(f));
    return r;
}
__device__ __forceinline__ float tf32r(float f) { return __uint_as_float(f2tf32(f)); }

__device__ __forceinline__ void cp_async16(float* dst_smem, const float* src_gmem) {
    uint32_t d = (uint32_t)__cvta_generic_to_shared(dst_smem);
    asm volatile("cp.async.cg.shared.global [%0], [%1], 16;\n" :: "r"(d), "l"(src_gmem));
}
__device__ __forceinline__ void cp_commit() {
    asm volatile("cp.async.commit_group;\n" ::: "memory");
}
template<int N> __device__ __forceinline__ void cp_wait() {
    asm volatile("cp.async.wait_group %0;\n" :: "n"(N) : "memory");
}

// Kernel 1: fragment-packed W with (1+3.38e-4) bias pre-scale + tf32-RNA.
// Scale cancels first-order truncation bias of raw-fp32 X bits in the tf32 MMA.
__global__ void lla_weights_kernel(const float* __restrict__ alpha,
                                   const float* __restrict__ ke) {
    const int b = blockIdx.x;
    __shared__ float a_s[NEXP];
    if (threadIdx.x < NEXP) a_s[threadIdx.x] = alpha[b * NEXP + threadIdx.x];
    __syncthreads();
#pragma unroll
    for (int ent = 0; ent < 4; ent++) {
        int id = ent * 256 + threadIdx.x;   // 0..1023
        int l  = id & 31;
        int km = id >> 5;                   // k*4 + m
        int m  = km & 3, k = km >> 2;
        int g  = l >> 2, t = l & 3;
        int r0 = m * 16 + g, r1 = r0 + 8;
        int c0 = k * 8 + t,  c1 = c0 + 4;
        float s00 = 0.f, s10 = 0.f, s01 = 0.f, s11 = 0.f;
#pragma unroll
        for (int e = 0; e < NEXP; e++) {
            const float* kb = ke + e * COUT * CIN;
            float a = a_s[e];
            s00 = fmaf(a, kb[r0 * 64 + c0], s00);
            s10 = fmaf(a, kb[r1 * 64 + c0], s10);
            s01 = fmaf(a, kb[r0 * 64 + c1], s01);
            s11 = fmaf(a, kb[r1 * 64 + c1], s11);
        }
        g_W2[b * 1024 + id] = make_float4(
            tf32r(s00 * 1.000338f), tf32r(s10 * 1.000338f),
            tf32r(s01 * 1.000338f), tf32r(s11 * 1.000338f));
    }
}

// Kernel 2: 128-thread CTAs, 5 CTAs/SM. Warp w owns M-rows [16w,16w+16);
// CTA shares a depth-4 cp.async ring of 32-px X tiles (XOR-swizzled 8KB
// stages). W fragments live in 32 regs (one-time LDG from packed g_W2).
// Per tile: wait<2> (tile resident) -> sync -> prefetch+commit -> compute.
__global__ __launch_bounds__(128, 5)
void lla_conv_kernel(const float* __restrict__ x, float* __restrict__ out) {
    extern __shared__ float smem[];

    const int b    = blockIdx.y;
    const int tid  = threadIdx.x;
    const int lane = tid & 31;
    const int warp = tid >> 5;
    const int g    = lane >> 2;     // 0..7
    const int tig  = lane & 3;      // 0..3
    const int m0   = warp * 16;

    const float* xb = x   + (size_t)b * CIN  * HW;
    float*       ob = out + (size_t)b * COUT * HW;
    const int pbase = blockIdx.x * (NPX * NT);

    // ---- One-time A fragments: 8 LDG.128 from packed W table ----
    const float4* wf = g_W2 + b * 1024 + lane;
    uint32_t afr[8][4];
#pragma unroll
    for (int k = 0; k < 8; k++) {
        float4 a = __ldg(wf + (k * 4 + warp) * 32);
        afr[k][0] = __float_as_uint(a.x); afr[k][1] = __float_as_uint(a.y);
        afr[k][2] = __float_as_uint(a.z); afr[k][3] = __float_as_uint(a.w);
    }

    // ---- Prologue: tiles 0..2 into stages 0..2 (3 committed groups) ----
    // 512 chunks/stage; thread -> (row = id>>3, q = id&7), qs = q^((row&3)<<1)
#pragma unroll
    for (int t = 0; t < NBUF - 1; t++) {
#pragma unroll
        for (int i = 0; i < 4; i++) {
            int id  = tid + 128 * i;
            int row = id >> 3;
            int q   = id & 7;
            int qs  = q ^ ((row & 3) << 1);
            cp_async16(smem + t * TILEF + row * XS + qs * 4,
                       xb + row * HW + pbase + t * NPX + q * 4);
        }
        cp_commit();
    }

    for (int it = 0; it < NT; it++) {
        float* const cur = smem + (it & (NBUF - 1)) * TILEF;
        const int p0 = pbase + it * NPX;

        // Outstanding groups here cover tiles it..it+2; leaving <=2 pending
        // guarantees tile 'it' has fully landed (the R12 bug was wait<3>).
        cp_wait<NBUF - 2>();
        __syncthreads();       // cross-thread visibility + stage-reuse safety

        // ---- Prefetch tile it+3 into stage (it+3)&3 (last read at it-1) ----
        if (it + NBUF - 1 < NT) {
            float* const nxt = smem + ((it + NBUF - 1) & (NBUF - 1)) * TILEF;
            const int pn = p0 + (NBUF - 1) * NPX;
#pragma unroll
            for (int i = 0; i < 4; i++) {
                int id  = tid + 128 * i;
                int row = id >> 3;
                int q   = id & 7;
                int qs  = q ^ ((row & 3) << 1);
                cp_async16(nxt + row * XS + qs * 4, xb + row * HW + pn + q * 4);
            }
        }
        cp_commit();           // always commit to keep group counts aligned

        // ---- Compute: 4 n-subtiles x 8 k-steps, M=16 per warp ----
        float acc[4][4];
#pragma unroll
        for (int nt = 0; nt < 4; nt++) {
            acc[nt][0] = 0.f; acc[nt][1] = 0.f;
            acc[nt][2] = 0.f; acc[nt][3] = 0.f;
        }
#pragma unroll
        for (int k = 0; k < 8; k++) {
            const int r0 = k * 8 + tig;        // b0 row
            const int r1 = r0 + 4;             // b1 row (same low-2 bits)
            const int sw = ((r0 & 3) << 1);
#pragma unroll
            for (int nt = 0; nt < 4; nt++) {
                const int c  = nt * 8 + g;
                const int ci = (((c >> 2) ^ sw) << 2) + (c & 3);
                uint32_t b0 = __float_as_uint(cur[r0 * XS + ci]);
                uint32_t b1 = __float_as_uint(cur[r1 * XS + ci]);
                asm volatile(
                    "mma.sync.aligned.m16n8k8.row.col.f32.tf32.tf32.f32 "
                    "{%0,%1,%2,%3}, {%4,%5,%6,%7}, {%8,%9}, {%0,%1,%2,%3};\n"
                    : "+f"(acc[nt][0]), "+f"(acc[nt][1]),
                      "+f"(acc[nt][2]), "+f"(acc[nt][3])
                    : "r"(afr[k][0]), "r"(afr[k][1]),
                      "r"(afr[k][2]), "r"(afr[k][3]),
                      "r"(b0), "r"(b1));
            }
        }

        // ---- Streaming stores: full 32B sectors per (row, nt) ----
#pragma unroll
        for (int nt = 0; nt < 4; nt++) {
            const int c = p0 + nt * 8 + 2 * tig;
            float2 v0 = make_float2(acc[nt][0], acc[nt][1]);
            float2 v1 = make_float2(acc[nt][2], acc[nt][3]);
            __stcs(reinterpret_cast<float2*>(ob + (size_t)(m0 + g)     * HW + c), v0);
            __stcs(reinterpret_cast<float2*>(ob + (size_t)(m0 + 8 + g) * HW + c), v1);
        }
    }
}

extern "C" void kernel_launch(void* const* d_in, const int* in_sizes, int n_in,
                              void* d_out, int out_size) {
    const float* x     = (const float*)d_in[0];   // [32,64,160,160]
    const float* alpha = (const float*)d_in[1];   // [32,8]
    const float* ke    = (const float*)d_in[2];   // [8,64,64,1,1]
    float*       out   = (float*)d_out;           // [32,64,160,160]

    cudaFuncSetAttribute(lla_conv_kernel,
                         cudaFuncAttributeMaxDynamicSharedMemorySize, SMEM_BYTES);

    lla_weights_kernel<<<BATCH, 256>>>(alpha, ke);

    dim3 grid(HW / (NPX * NT), BATCH);            // (25, 32)
    lla_conv_kernel<<<grid, 128, SMEM_BYTES>>>(x, out);
}

// round 17
// speedup vs baseline: 1.8606x; 1.1527x over previous
#include <cuda_runtime.h>
#include <cstdint>

// Problem constants
#define BATCH 32
#define NEXP 8
#define CIN 64
#define COUT 64
#define HW 25600            // 160*160
#define NPX 32              // pixels per CTA-tile
#define NT 32               // tiles per CTA -> 1024-px strip
#define XS 32               // smem row stride in floats (XOR-swizzled, no pad)
#define TILEF (CIN * XS)    // 2048 floats = 8KB per stage
#define NBUF 5
#define SMEM_BYTES (NBUF * TILEF * 4)   // 40960 -> 5 CTAs/SM (200KB)

// Fragment-packed, TF32-rounded W: g_W2[b][(k*4+m)*32 + lane] =
//   {W[m16+g][k8+t], W[m16+8+g][k8+t], W[m16+g][k8+t+4], W[m16+8+g][k8+t+4]}
__device__ float4 g_W2[BATCH * 1024];

__device__ __forceinline__ uint32_t f2tf32(float f) {
    uint32_t r;
    asm("cvt.rna.tf32.f32 %0, %1;" : "=r"(r) : "f"(f));
    return r;
}
__device__ __forceinline__ float tf32r(float f) { return __uint_as_float(f2tf32(f)); }

__device__ __forceinline__ void cp_async16(float* dst_smem, const float* src_gmem) {
    uint32_t d = (uint32_t)__cvta_generic_to_shared(dst_smem);
    asm volatile("cp.async.cg.shared.global [%0], [%1], 16;\n" :: "r"(d), "l"(src_gmem));
}
__device__ __forceinline__ void cp_commit() {
    asm volatile("cp.async.commit_group;\n" ::: "memory");
}
template<int N> __device__ __forceinline__ void cp_wait() {
    asm volatile("cp.async.wait_group %0;\n" :: "n"(N) : "memory");
}

// Kernel 1: coalesced-read weights kernel. Threads walk W linearly
// (ke reads fully coalesced); packed destination computed analytically.
// (1+3.38e-4) pre-scale cancels tf32-truncation bias of raw X bits.
__global__ void lla_weights_kernel(const float* __restrict__ alpha,
                                   const float* __restrict__ ke) {
    const int b = blockIdx.x;
    __shared__ float a_s[NEXP];
    if (threadIdx.x < NEXP) a_s[threadIdx.x] = alpha[b * NEXP + threadIdx.x];
    __syncthreads();
    float* const Wb = reinterpret_cast<float*>(g_W2) + b * 4096;
    int idx = blockIdx.y * 1024 + threadIdx.x;
#pragma unroll
    for (int j = 0; j < 4; j++, idx += 256) {
        float s = 0.f;
#pragma unroll
        for (int e = 0; e < NEXP; e++)
            s = fmaf(a_s[e], ke[e * 4096 + idx], s);
        s = tf32r(s * 1.000338f);
        // idx = o*64 + i  ->  packed fragment position
        const int o = idx >> 6, i = idx & 63;
        const int m = o >> 4, g = o & 7, half = (o >> 3) & 1;
        const int k = i >> 3, t = i & 3, hi = (i >> 2) & 1;
        const int l = (g << 2) | t;
        const int c = half | (hi << 1);
        Wb[((((k << 2) + m) * 32 + l) << 2) | c] = s;
    }
}

// Kernel 2: 128-thread CTAs, 5 CTAs/SM. Warp w owns M-rows [16w,16w+16);
// CTA shares a depth-5 cp.async ring of 32-px X tiles (XOR-swizzled 8KB
// stages; 4 tiles in flight). W fragments in 32 regs from packed g_W2.
// Per tile: wait<3> (tile resident) -> sync -> prefetch+commit -> compute.
__global__ __launch_bounds__(128, 5)
void lla_conv_kernel(const float* __restrict__ x, float* __restrict__ out) {
    extern __shared__ float smem[];

    const int b    = blockIdx.y;
    const int tid  = threadIdx.x;
    const int lane = tid & 31;
    const int warp = tid >> 5;
    const int g    = lane >> 2;     // 0..7
    const int tig  = lane & 3;      // 0..3
    const int m0   = warp * 16;

    const float* xb = x   + (size_t)b * CIN  * HW;
    float*       ob = out + (size_t)b * COUT * HW;
    const int pbase = blockIdx.x * (NPX * NT);

    // ---- One-time A fragments: 8 LDG.128 from packed W table ----
    const float4* wf = g_W2 + b * 1024 + lane;
    uint32_t afr[8][4];
#pragma unroll
    for (int k = 0; k < 8; k++) {
        float4 a = __ldg(wf + (k * 4 + warp) * 32);
        afr[k][0] = __float_as_uint(a.x); afr[k][1] = __float_as_uint(a.y);
        afr[k][2] = __float_as_uint(a.z); afr[k][3] = __float_as_uint(a.w);
    }

    // ---- Prologue: tiles 0..3 into stages 0..3 (4 committed groups) ----
    // 512 chunks/stage; thread -> (row = id>>3, q = id&7), qs = q^((row&3)<<1)
#pragma unroll
    for (int t = 0; t < NBUF - 1; t++) {
#pragma unroll
        for (int i = 0; i < 4; i++) {
            int id  = tid + 128 * i;
            int row = id >> 3;
            int q   = id & 7;
            int qs  = q ^ ((row & 3) << 1);
            cp_async16(smem + t * TILEF + row * XS + qs * 4,
                       xb + row * HW + pbase + t * NPX + q * 4);
        }
        cp_commit();
    }

    int cst = 0;            // current stage
    int nst = NBUF - 1;     // prefetch stage (it + NBUF-1)
    for (int it = 0; it < NT; it++) {
        float* const cur = smem + cst * TILEF;
        const int p0 = pbase + it * NPX;

        // Outstanding real groups cover tiles it..it+3; empty groups (tail)
        // are newest, so wait<3> always forces tile 'it' complete.
        cp_wait<NBUF - 2>();
        __syncthreads();       // cross-thread visibility + stage-reuse safety

        // ---- Prefetch tile it+4 into stage nst (last read at it-1) ----
        if (it + NBUF - 1 < NT) {
            float* const nxt = smem + nst * TILEF;
            const int pn = p0 + (NBUF - 1) * NPX;
#pragma unroll
            for (int i = 0; i < 4; i++) {
                int id  = tid + 128 * i;
                int row = id >> 3;
                int q   = id & 7;
                int qs  = q ^ ((row & 3) << 1);
                cp_async16(nxt + row * XS + qs * 4, xb + row * HW + pn + q * 4);
            }
        }
        cp_commit();           // always commit to keep group order aligned

        // ---- Compute: 4 n-subtiles x 8 k-steps, M=16 per warp ----
        float acc[4][4];
#pragma unroll
        for (int nt = 0; nt < 4; nt++) {
            acc[nt][0] = 0.f; acc[nt][1] = 0.f;
            acc[nt][2] = 0.f; acc[nt][3] = 0.f;
        }
#pragma unroll
        for (int k = 0; k < 8; k++) {
            const int r0 = k * 8 + tig;        // b0 row
            const int r1 = r0 + 4;             // b1 row (same low-2 bits)
            const int sw = ((r0 & 3) << 1);
#pragma unroll
            for (int nt = 0; nt < 4; nt++) {
                const int c  = nt * 8 + g;
                const int ci = (((c >> 2) ^ sw) << 2) + (c & 3);
                uint32_t b0 = __float_as_uint(cur[r0 * XS + ci]);
                uint32_t b1 = __float_as_uint(cur[r1 * XS + ci]);
                asm volatile(
                    "mma.sync.aligned.m16n8k8.row.col.f32.tf32.tf32.f32 "
                    "{%0,%1,%2,%3}, {%4,%5,%6,%7}, {%8,%9}, {%0,%1,%2,%3};\n"
                    : "+f"(acc[nt][0]), "+f"(acc[nt][1]),
                      "+f"(acc[nt][2]), "+f"(acc[nt][3])
                    : "r"(afr[k][0]), "r"(afr[k][1]),
                      "r"(afr[k][2]), "r"(afr[k][3]),
                      "r"(b0), "r"(b1));
            }
        }

        // ---- Streaming stores: full 32B sectors per (row, nt) ----
#pragma unroll
        for (int nt = 0; nt < 4; nt++) {
            const int c = p0 + nt * 8 + 2 * tig;
            float2 v0 = make_float2(acc[nt][0], acc[nt][1]);
            float2 v1 = make_float2(acc[nt][2], acc[nt][3]);
            __stcs(reinterpret_cast<float2*>(ob + (size_t)(m0 + g)     * HW + c), v0);
            __stcs(reinterpret_cast<float2*>(ob + (size_t)(m0 + 8 + g) * HW + c), v1);
        }

        cst = (cst + 1 == NBUF) ? 0 : cst + 1;
        nst = (nst + 1 == NBUF) ? 0 : nst + 1;
    }
}

extern "C" void kernel_launch(void* const* d_in, const int* in_sizes, int n_in,
                              void* d_out, int out_size) {
    const float* x     = (const float*)d_in[0];   // [32,64,160,160]
    const float* alpha = (const float*)d_in[1];   // [32,8]
    const float* ke    = (const float*)d_in[2];   // [8,64,64,1,1]
    float*       out   = (float*)d_out;           // [32,64,160,160]

    cudaFuncSetAttribute(lla_conv_kernel,
                         cudaFuncAttributeMaxDynamicSharedMemorySize, SMEM_BYTES);

    dim3 wgrid(BATCH, 4);
    lla_weights_kernel<<<wgrid, 256>>>(alpha, ke);

    dim3 grid(HW / (NPX * NT), BATCH);            // (25, 32)
    lla_conv_kernel<<<grid, 128, SMEM_BYTES>>>(x, out);
}